// round 1
// baseline (speedup 1.0000x reference)
#include <cuda_runtime.h>
#include <math.h>

#define B_   4
#define C_   2048
#define D_   1024
#define H_   16
#define HD_  64
#define KS_  512          // C_/STRIDE
#define STRIDE_ 4
#define EPS_ 1.1920929e-07f

// ---------------- scratch (device globals, zero-init, no allocs) -------------
__device__ float g_xqn [B_*C_*D_];        // rmsnorm(x, rmsq_w), all rows
__device__ float g_xkvn[B_*KS_*D_];       // rmsnorm(x, rmskv_w), strided rows only
__device__ float g_q   [B_*C_*D_];        // q projection output
__device__ float g_kv  [B_*KS_*2*D_];     // kv projection output (strided rows)
__device__ float g_qn  [B_*H_*C_*HD_];    // rope+norm q, (b,h,c,hd)
__device__ float g_kn  [B_*H_*KS_*HD_];   // rope+norm k, (b,h,ks,hd)
__device__ float g_v   [B_*H_*KS_*HD_];   // v, (b,h,ks,hd)
__device__ float g_attn[B_*C_*D_];        // attention output, (b,c,h*hd)
__device__ float g_base[HD_/2];           // rope freq base

// ---------------- rope base init (fp64 for bit-level safety) -----------------
__global__ void init_base_kernel() {
    int i = threadIdx.x;                       // 32 threads
    double end = 2595.0 * log10(21.0);         // 2595*log10(1+4000/200)
    double v = (double)i * (end / 31.0);
    double scale = pow(10.0, v / 2595.0) - 1.0;
    g_base[i] = (float)(200.0 * scale / 1000.0);
}

// ---------------- dual rmsnorm: xqn (all rows) + xkvn (strided, compacted) ---
__global__ void rmsnorm_dual_kernel(const float* __restrict__ x,
                                    const float* __restrict__ wq,
                                    const float* __restrict__ wkv) {
    int row = blockIdx.x;                       // 0..8191
    int tid = threadIdx.x;                      // 256
    const float* xr = x + (size_t)row * D_;
    float v[4]; float ss = 0.f;
#pragma unroll
    for (int i = 0; i < 4; i++) { v[i] = xr[tid + i*256]; ss += v[i]*v[i]; }
#pragma unroll
    for (int o = 16; o; o >>= 1) ss += __shfl_xor_sync(0xffffffffu, ss, o);
    __shared__ float red[8];
    if ((tid & 31) == 0) red[tid >> 5] = ss;
    __syncthreads();
    float tot = 0.f;
#pragma unroll
    for (int i = 0; i < 8; i++) tot += red[i];
    float r = rsqrtf(tot * (1.f / D_) + EPS_);

    int b = row >> 11, c = row & (C_ - 1);
    bool dokv = (c & (STRIDE_ - 1)) == 0;
    int krow = b * KS_ + (c >> 2);
#pragma unroll
    for (int i = 0; i < 4; i++) {
        int col = tid + i*256;
        float n = v[i] * r;
        g_xqn[(size_t)row * D_ + col] = n * wq[col];
        if (dokv) g_xkvn[(size_t)krow * D_ + col] = n * wkv[col];
    }
}

// ---------------- classic 128x128x8 SGEMM with bias --------------------------
// C[M,N] = A[M,K] @ B[K,N] + bias[N]; all row-major; M%128==0, N%128==0, K%8==0
__global__ __launch_bounds__(256) void sgemm_bias_kernel(
        const float* __restrict__ A, const float* __restrict__ Bm,
        const float* __restrict__ bias, float* __restrict__ C,
        int M, int N, int K) {
    __shared__ float As[8][128];
    __shared__ float Bs[8][128];
    int tid = threadIdx.x;
    int brow = blockIdx.y * 128;
    int bcol = blockIdx.x * 128;
    int trow = (tid / 16) * 8;
    int tcol = (tid % 16) * 8;
    int aRow = tid >> 1;
    int aCol = (tid & 1) * 4;
    int bRow = tid >> 5;
    int bCol = (tid & 31) * 4;

    float acc[8][8];
#pragma unroll
    for (int i = 0; i < 8; i++)
#pragma unroll
        for (int j = 0; j < 8; j++) acc[i][j] = 0.f;

    for (int k0 = 0; k0 < K; k0 += 8) {
        float4 a4 = *(const float4*)(A + (size_t)(brow + aRow) * K + k0 + aCol);
        As[aCol + 0][aRow] = a4.x;
        As[aCol + 1][aRow] = a4.y;
        As[aCol + 2][aRow] = a4.z;
        As[aCol + 3][aRow] = a4.w;
        float4 b4 = *(const float4*)(Bm + (size_t)(k0 + bRow) * N + bcol + bCol);
        *(float4*)&Bs[bRow][bCol] = b4;
        __syncthreads();
#pragma unroll
        for (int kk = 0; kk < 8; kk++) {
            float af[8], bf[8];
#pragma unroll
            for (int i = 0; i < 8; i++) af[i] = As[kk][trow + i];
#pragma unroll
            for (int j = 0; j < 8; j++) bf[j] = Bs[kk][tcol + j];
#pragma unroll
            for (int i = 0; i < 8; i++)
#pragma unroll
                for (int j = 0; j < 8; j++) acc[i][j] += af[i] * bf[j];
        }
        __syncthreads();
    }
#pragma unroll
    for (int i = 0; i < 8; i++) {
        float* crow = C + (size_t)(brow + trow + i) * N + bcol + tcol;
#pragma unroll
        for (int j = 0; j < 8; j++) crow[j] = acc[i][j] + bias[bcol + tcol + j];
    }
}

// ---------------- rope + per-head rmsnorm on Q --------------------------------
__global__ void rope_norm_q_kernel(const float* __restrict__ ln_w) {
    int row = blockIdx.x;                 // b*2048 + c
    int h = threadIdx.x >> 5;             // 512 threads = 16 warps = 16 heads
    int lane = threadIdx.x & 31;
    int b = row >> 11, c = row & (C_ - 1);
    const float* qp = g_q + (size_t)row * D_ + h * HD_;
    float a  = qp[2 * lane];
    float bb = qp[2 * lane + 1];
    float fr = (float)c * g_base[lane];
    float sn, cs; sincosf(fr, &sn, &cs);
    float na = a * cs - bb * sn;
    float nb = a * sn + bb * cs;
    float ss = na * na + nb * nb;
#pragma unroll
    for (int o = 16; o; o >>= 1) ss += __shfl_xor_sync(0xffffffffu, ss, o);
    float r = rsqrtf(ss * (1.f / HD_) + EPS_);
    size_t ob = (((size_t)(b * H_ + h) * C_) + c) * HD_ + 2 * lane;
    g_qn[ob]     = na * r * ln_w[2 * lane];
    g_qn[ob + 1] = nb * r * ln_w[2 * lane + 1];
}

// ---------------- rope + rmsnorm on K (strided rows) + V copy ----------------
__global__ void kv_process_kernel(const float* __restrict__ ln_w) {
    int idx = blockIdx.x;                  // b*512 + ks
    int b = idx >> 9, ks = idx & (KS_ - 1);
    int h = threadIdx.x >> 5;              // 512 threads, warp = head
    int lane = threadIdx.x & 31;
    const float* row = g_kv + (size_t)idx * (2 * D_);
    // K half (cols 0..1023), rope at t = ks*STRIDE
    float a  = row[h * HD_ + 2 * lane];
    float bb = row[h * HD_ + 2 * lane + 1];
    float fr = (float)(ks * STRIDE_) * g_base[lane];
    float sn, cs; sincosf(fr, &sn, &cs);
    float na = a * cs - bb * sn;
    float nb = a * sn + bb * cs;
    float ss = na * na + nb * nb;
#pragma unroll
    for (int o = 16; o; o >>= 1) ss += __shfl_xor_sync(0xffffffffu, ss, o);
    float r = rsqrtf(ss * (1.f / HD_) + EPS_);
    size_t kb = (((size_t)(b * H_ + h) * KS_) + ks) * HD_;
    g_kn[kb + 2 * lane]     = na * r * ln_w[2 * lane];
    g_kn[kb + 2 * lane + 1] = nb * r * ln_w[2 * lane + 1];
    // V half (cols 1024..2047), direct copy
    g_v[kb + lane]      = row[D_ + h * HD_ + lane];
    g_v[kb + lane + 32] = row[D_ + h * HD_ + lane + 32];
}

// ---------------- attention: per (b,h), 16 q rows per block ------------------
__global__ __launch_bounds__(256) void attention_kernel() {
    const int TQ = 16;
    __shared__ float Qs[TQ][65];
    __shared__ float Ks[32][65];
    __shared__ float Ss[TQ][516];
    int bh = blockIdx.y;                   // 0..63  (b*16+h)
    int qbase = blockIdx.x * TQ;
    int tid = threadIdx.x;                 // 256

    const float* qptr = g_qn + ((size_t)bh * C_ + qbase) * HD_;
#pragma unroll
    for (int i = 0; i < 4; i++) {
        int idx = tid + i * 256;
        Qs[idx >> 6][idx & 63] = qptr[idx];
    }
    __syncthreads();

    // phase 1: scores = (Q K^T) * 0.125
    int qr = tid >> 4;
    int kk = tid & 15;
    const float* kbase = g_kn + (size_t)bh * KS_ * HD_;
    for (int kc = 0; kc < KS_; kc += 32) {
        const float* kptr = kbase + (size_t)kc * HD_;
#pragma unroll
        for (int i = 0; i < 8; i++) {
            int idx = tid + i * 256;
            Ks[idx >> 6][idx & 63] = kptr[idx];
        }
        __syncthreads();
        float s0 = 0.f, s1 = 0.f;
#pragma unroll
        for (int d = 0; d < HD_; d++) {
            float qv = Qs[qr][d];
            s0 += qv * Ks[kk][d];
            s1 += qv * Ks[kk + 16][d];
        }
        Ss[qr][kc + kk]      = s0 * 0.125f;
        Ss[qr][kc + kk + 16] = s1 * 0.125f;
        __syncthreads();
    }

    // phase 2: softmax per row (warp per 2 rows)
    int wid = tid >> 5, lane = tid & 31;
    for (int r = wid; r < TQ; r += 8) {
        float m = -1e30f;
        for (int j = lane; j < KS_; j += 32) m = fmaxf(m, Ss[r][j]);
#pragma unroll
        for (int o = 16; o; o >>= 1) m = fmaxf(m, __shfl_xor_sync(0xffffffffu, m, o));
        float sum = 0.f;
        for (int j = lane; j < KS_; j += 32) {
            float e = expf(Ss[r][j] - m);
            Ss[r][j] = e;
            sum += e;
        }
#pragma unroll
        for (int o = 16; o; o >>= 1) sum += __shfl_xor_sync(0xffffffffu, sum, o);
        float inv = 1.f / sum;
        for (int j = lane; j < KS_; j += 32) Ss[r][j] *= inv;
    }
    __syncthreads();

    // phase 3: O = P @ V
    int hd = tid & 63;
    int ty = tid >> 6;                     // 0..3
    float o0 = 0.f, o1 = 0.f, o2 = 0.f, o3 = 0.f;
    const float* vptr = g_v + (size_t)bh * KS_ * HD_;
#pragma unroll 4
    for (int ks = 0; ks < KS_; ks++) {
        float vv = vptr[(size_t)ks * HD_ + hd];
        o0 += Ss[ty][ks] * vv;
        o1 += Ss[ty + 4][ks] * vv;
        o2 += Ss[ty + 8][ks] * vv;
        o3 += Ss[ty + 12][ks] * vv;
    }
    int b = bh >> 4, h = bh & 15;
    size_t orow = ((size_t)b * C_ + qbase) * D_ + h * HD_ + hd;
    g_attn[orow + (size_t)(ty)      * D_] = o0;
    g_attn[orow + (size_t)(ty + 4)  * D_] = o1;
    g_attn[orow + (size_t)(ty + 8)  * D_] = o2;
    g_attn[orow + (size_t)(ty + 12) * D_] = o3;
}

// ---------------- launcher ----------------------------------------------------
extern "C" void kernel_launch(void* const* d_in, const int* in_sizes, int n_in,
                              void* d_out, int out_size) {
    const float* x       = (const float*)d_in[0];
    const float* rmsq_w  = (const float*)d_in[1];
    const float* q_w     = (const float*)d_in[2];
    const float* q_b     = (const float*)d_in[3];
    const float* rmskv_w = (const float*)d_in[4];
    const float* kv_w    = (const float*)d_in[5];
    const float* kv_b    = (const float*)d_in[6];
    const float* ln_w    = (const float*)d_in[7];
    const float* out_w   = (const float*)d_in[8];
    const float* out_b   = (const float*)d_in[9];
    float* out = (float*)d_out;

    void *p_xqn, *p_xkvn, *p_q, *p_kv, *p_attn;
    cudaGetSymbolAddress(&p_xqn,  g_xqn);
    cudaGetSymbolAddress(&p_xkvn, g_xkvn);
    cudaGetSymbolAddress(&p_q,    g_q);
    cudaGetSymbolAddress(&p_kv,   g_kv);
    cudaGetSymbolAddress(&p_attn, g_attn);

    init_base_kernel<<<1, 32>>>();
    rmsnorm_dual_kernel<<<B_ * C_, 256>>>(x, rmsq_w, rmskv_w);

    // q = xqn @ q_w + q_b : M=8192, N=1024, K=1024
    sgemm_bias_kernel<<<dim3(D_ / 128, (B_ * C_) / 128), 256>>>(
        (const float*)p_xqn, q_w, q_b, (float*)p_q, B_ * C_, D_, D_);

    // kv = xkvn @ kv_w + kv_b (strided rows only): M=2048, N=2048, K=1024
    sgemm_bias_kernel<<<dim3((2 * D_) / 128, (B_ * KS_) / 128), 256>>>(
        (const float*)p_xkvn, kv_w, kv_b, (float*)p_kv, B_ * KS_, 2 * D_, D_);

    rope_norm_q_kernel<<<B_ * C_, 512>>>(ln_w);
    kv_process_kernel<<<B_ * KS_, 512>>>(ln_w);

    attention_kernel<<<dim3(C_ / 16, B_ * H_), 256>>>();

    // out = attn @ out_w + out_b : M=8192, N=1024, K=1024
    sgemm_bias_kernel<<<dim3(D_ / 128, (B_ * C_) / 128), 256>>>(
        (const float*)p_attn, out_w, out_b, out, B_ * C_, D_, D_);
}

// round 4
// speedup vs baseline: 1.9808x; 1.9808x over previous
#include <cuda_runtime.h>
#include <math.h>
#include <stdint.h>
#include <mma.h>

using namespace nvcuda;

#define B_   4
#define C_   2048
#define D_   1024
#define H_   16
#define HD_  64
#define KS_  512
#define STRIDE_ 4
#define EPS_ 1.1920929e-07f

// ---------------- scratch (device globals) -----------------------------------
__device__ float g_xqn [B_*C_*D_];
__device__ float g_xkvn[B_*KS_*D_];
__device__ float g_q   [B_*C_*D_];
__device__ float g_kv  [B_*KS_*2*D_];
__device__ float g_qn  [B_*H_*C_*HD_];
__device__ float g_kn  [B_*H_*KS_*HD_];
__device__ float g_v   [B_*H_*KS_*HD_];
__device__ float g_attn[B_*C_*D_];
__device__ float g_base[HD_/2];

__device__ __forceinline__ float to_tf32(float x) {
    float r; asm("cvt.rna.tf32.f32 %0, %1;" : "=f"(r) : "f"(x)); return r;
}

// =================== wmma tf32 GEMM: C = A[M,K] @ W[K,N] + bias ===============
// 128x128 CTA tile, K-chunk 32, 8 warps (2m x 4n), warp tile 64x32.
// smem mainloop: As[2][128][36] + Bs[2][32][132] = 17664 floats
// smem epilogue: 8 warps * 64*36 = 18432 floats  (ld 36 = 144B, 16B multiple)
#define GA_LD 36
#define GB_LD 132
#define EP_LD 36
__global__ __launch_bounds__(256) void gemm_wmma_kernel(
        const float* __restrict__ A, const float* __restrict__ W,
        const float* __restrict__ bias, float* __restrict__ C,
        int M, int N, int K) {
    extern __shared__ float sm[];
    float* As = sm;              // 2*128*36 = 9216
    float* Bs = sm + 9216;       // 2*32*132 = 8448

    int tid = threadIdx.x;
    int warp = tid >> 5;
    int lane = tid & 31;
    int wm = warp & 1;           // m offset wm*64
    int wn = warp >> 1;          // n offset wn*32
    int m0 = blockIdx.y * 128;
    int n0 = blockIdx.x * 128;

    wmma::fragment<wmma::accumulator, 16, 16, 8, float> acc[4][2];
#pragma unroll
    for (int i = 0; i < 4; i++)
#pragma unroll
        for (int j = 0; j < 2; j++) wmma::fill_fragment(acc[i][j], 0.0f);

    // stage chunk 0 into buf 0
    {
#pragma unroll
        for (int i = 0; i < 4; i++) {
            int u = tid + i * 256;
            int r = u >> 3, q = u & 7;
            float4 v = *(const float4*)(A + (size_t)(m0 + r) * K + q * 4);
            float* d = As + r * GA_LD + q * 4;
            d[0] = to_tf32(v.x); d[1] = to_tf32(v.y);
            d[2] = to_tf32(v.z); d[3] = to_tf32(v.w);
        }
#pragma unroll
        for (int i = 0; i < 4; i++) {
            int u = tid + i * 256;
            int r = u >> 5, q = u & 31;
            float4 v = *(const float4*)(W + (size_t)r * N + n0 + q * 4);
            float* d = Bs + r * GB_LD + q * 4;
            d[0] = to_tf32(v.x); d[1] = to_tf32(v.y);
            d[2] = to_tf32(v.z); d[3] = to_tf32(v.w);
        }
    }
    __syncthreads();

    int nc = K >> 5;
    for (int c = 0; c < nc; c++) {
        int buf = c & 1;
        float4 pa[4], pb[4];
        if (c + 1 < nc) {
#pragma unroll
            for (int i = 0; i < 4; i++) {
                int u = tid + i * 256;
                int r = u >> 3, q = u & 7;
                pa[i] = *(const float4*)(A + (size_t)(m0 + r) * K + (c + 1) * 32 + q * 4);
            }
#pragma unroll
            for (int i = 0; i < 4; i++) {
                int u = tid + i * 256;
                int r = u >> 5, q = u & 31;
                pb[i] = *(const float4*)(W + (size_t)((c + 1) * 32 + r) * N + n0 + q * 4);
            }
        }
        const float* Ab = As + buf * (128 * GA_LD);
        const float* Bb = Bs + buf * (32 * GB_LD);
#pragma unroll
        for (int ks = 0; ks < 4; ks++) {
            wmma::fragment<wmma::matrix_a, 16, 16, 8, wmma::precision::tf32, wmma::row_major> af[4];
            wmma::fragment<wmma::matrix_b, 16, 16, 8, wmma::precision::tf32, wmma::row_major> bf[2];
#pragma unroll
            for (int i = 0; i < 4; i++)
                wmma::load_matrix_sync(af[i], Ab + (wm * 64 + i * 16) * GA_LD + ks * 8, GA_LD);
#pragma unroll
            for (int j = 0; j < 2; j++)
                wmma::load_matrix_sync(bf[j], Bb + (ks * 8) * GB_LD + wn * 32 + j * 16, GB_LD);
#pragma unroll
            for (int i = 0; i < 4; i++)
#pragma unroll
                for (int j = 0; j < 2; j++)
                    wmma::mma_sync(acc[i][j], af[i], bf[j], acc[i][j]);
        }
        if (c + 1 < nc) {
            int ob = 1 - buf;
            float* Ad = As + ob * (128 * GA_LD);
            float* Bd = Bs + ob * (32 * GB_LD);
#pragma unroll
            for (int i = 0; i < 4; i++) {
                int u = tid + i * 256;
                int r = u >> 3, q = u & 7;
                float* d = Ad + r * GA_LD + q * 4;
                d[0] = to_tf32(pa[i].x); d[1] = to_tf32(pa[i].y);
                d[2] = to_tf32(pa[i].z); d[3] = to_tf32(pa[i].w);
            }
#pragma unroll
            for (int i = 0; i < 4; i++) {
                int u = tid + i * 256;
                int r = u >> 5, q = u & 31;
                float* d = Bd + r * GB_LD + q * 4;
                d[0] = to_tf32(pb[i].x); d[1] = to_tf32(pb[i].y);
                d[2] = to_tf32(pb[i].z); d[3] = to_tf32(pb[i].w);
            }
        }
        __syncthreads();
    }

    // epilogue: per-warp smem staging (ld 36 = 144B, legal) + bias + stores
    float* wsm = sm + warp * (64 * EP_LD);
#pragma unroll
    for (int i = 0; i < 4; i++)
#pragma unroll
        for (int j = 0; j < 2; j++)
            wmma::store_matrix_sync(wsm + (i * 16) * EP_LD + j * 16, acc[i][j], EP_LD,
                                    wmma::mem_row_major);
    __syncwarp();
#pragma unroll
    for (int r2 = 0; r2 < 2; r2++) {
        int r = r2 * 32 + lane;
        float* crow = C + (size_t)(m0 + wm * 64 + r) * N + n0 + wn * 32;
        const float* srow = wsm + r * EP_LD;
        const float* brow = bias + n0 + wn * 32;
#pragma unroll
        for (int q = 0; q < 8; q++) {
            float4 v;
            v.x = srow[q * 4 + 0] + brow[q * 4 + 0];
            v.y = srow[q * 4 + 1] + brow[q * 4 + 1];
            v.z = srow[q * 4 + 2] + brow[q * 4 + 2];
            v.w = srow[q * 4 + 3] + brow[q * 4 + 3];
            *(float4*)(crow + q * 4) = v;
        }
    }
}

// =================== fused wmma attention ====================================
// block: one bh, 64 q rows. smem: Qs[64][72], KVs[64][72], Ss[64][520]
#define AQ_LD 72
#define AS_LD 520
__global__ __launch_bounds__(256) void attention_wmma_kernel() {
    extern __shared__ float sm[];
    float* Qs  = sm;             // 4608
    float* KVs = sm + 4608;      // 4608
    float* Ss  = sm + 9216;      // 64*520 = 33280

    int tid = threadIdx.x;
    int warp = tid >> 5;
    int lane = tid & 31;
    int wm = warp & 3;           // 4 m-tiles of 16
    int wn = warp >> 2;          // 2 n-tiles of 32
    int bh = blockIdx.y;
    int qbase = blockIdx.x * 64;

    const float* qsrc = g_qn + ((size_t)bh * C_ + qbase) * HD_;
    const float* ksrc = g_kn + (size_t)bh * KS_ * HD_;
    const float* vsrc = g_v  + (size_t)bh * KS_ * HD_;

    // stage Q (tf32) and K chunk 0
#pragma unroll
    for (int i = 0; i < 4; i++) {
        int u = tid + i * 256;
        int r = u >> 4, q = u & 15;
        float4 v = *(const float4*)(qsrc + r * HD_ + q * 4);
        float* d = Qs + r * AQ_LD + q * 4;
        d[0] = to_tf32(v.x); d[1] = to_tf32(v.y);
        d[2] = to_tf32(v.z); d[3] = to_tf32(v.w);
    }
#pragma unroll
    for (int i = 0; i < 4; i++) {
        int u = tid + i * 256;
        int r = u >> 4, q = u & 15;
        float4 v = *(const float4*)(ksrc + r * HD_ + q * 4);
        float* d = KVs + r * AQ_LD + q * 4;
        d[0] = to_tf32(v.x); d[1] = to_tf32(v.y);
        d[2] = to_tf32(v.z); d[3] = to_tf32(v.w);
    }
    __syncthreads();

    // ---- scores: S[64][512] = Q @ K^T, chunks of 64 keys --------------------
    for (int ch = 0; ch < 8; ch++) {
        float4 pk[4];
        if (ch + 1 < 8) {
#pragma unroll
            for (int i = 0; i < 4; i++) {
                int u = tid + i * 256;
                int r = u >> 4, q = u & 15;
                pk[i] = *(const float4*)(ksrc + ((ch + 1) * 64 + r) * HD_ + q * 4);
            }
        }
        wmma::fragment<wmma::accumulator, 16, 16, 8, float> sacc[2];
#pragma unroll
        for (int j = 0; j < 2; j++) wmma::fill_fragment(sacc[j], 0.0f);
#pragma unroll
        for (int ks = 0; ks < 8; ks++) {
            wmma::fragment<wmma::matrix_a, 16, 16, 8, wmma::precision::tf32, wmma::row_major> af;
            wmma::fragment<wmma::matrix_b, 16, 16, 8, wmma::precision::tf32, wmma::col_major> bf[2];
            wmma::load_matrix_sync(af, Qs + (wm * 16) * AQ_LD + ks * 8, AQ_LD);
#pragma unroll
            for (int j = 0; j < 2; j++)
                wmma::load_matrix_sync(bf[j], KVs + (wn * 32 + j * 16) * AQ_LD + ks * 8, AQ_LD);
#pragma unroll
            for (int j = 0; j < 2; j++)
                wmma::mma_sync(sacc[j], af, bf[j], sacc[j]);
        }
#pragma unroll
        for (int j = 0; j < 2; j++) {
#pragma unroll
            for (int t = 0; t < sacc[j].num_elements; t++) sacc[j].x[t] *= 0.125f;
            wmma::store_matrix_sync(Ss + (wm * 16) * AS_LD + ch * 64 + wn * 32 + j * 16,
                                    sacc[j], AS_LD, wmma::mem_row_major);
        }
        if (ch + 1 < 8) {
            __syncthreads();
#pragma unroll
            for (int i = 0; i < 4; i++) {
                int u = tid + i * 256;
                int r = u >> 4, q = u & 15;
                float* d = KVs + r * AQ_LD + q * 4;
                d[0] = to_tf32(pk[i].x); d[1] = to_tf32(pk[i].y);
                d[2] = to_tf32(pk[i].z); d[3] = to_tf32(pk[i].w);
            }
        }
        __syncthreads();
    }

    // ---- softmax (warp w handles rows w*8..w*8+7), store P as tf32 ----------
    for (int rr = 0; rr < 8; rr++) {
        int r = warp * 8 + rr;
        float* row = Ss + r * AS_LD;
        float m = -1e30f;
#pragma unroll
        for (int k = 0; k < 16; k++) m = fmaxf(m, row[lane + k * 32]);
#pragma unroll
        for (int o = 16; o; o >>= 1) m = fmaxf(m, __shfl_xor_sync(0xffffffffu, m, o));
        float sum = 0.f;
        float e[16];
#pragma unroll
        for (int k = 0; k < 16; k++) { e[k] = expf(row[lane + k * 32] - m); sum += e[k]; }
#pragma unroll
        for (int o = 16; o; o >>= 1) sum += __shfl_xor_sync(0xffffffffu, sum, o);
        float inv = 1.f / sum;
#pragma unroll
        for (int k = 0; k < 16; k++) row[lane + k * 32] = to_tf32(e[k] * inv);
    }
    __syncthreads();

    // ---- O = P @ V, stream V chunks of 64 -----------------------------------
    wmma::fragment<wmma::accumulator, 16, 16, 8, float> oacc[2];
#pragma unroll
    for (int j = 0; j < 2; j++) wmma::fill_fragment(oacc[j], 0.0f);

    // stage V chunk 0
#pragma unroll
    for (int i = 0; i < 4; i++) {
        int u = tid + i * 256;
        int r = u >> 4, q = u & 15;
        float4 v = *(const float4*)(vsrc + r * HD_ + q * 4);
        float* d = KVs + r * AQ_LD + q * 4;
        d[0] = to_tf32(v.x); d[1] = to_tf32(v.y);
        d[2] = to_tf32(v.z); d[3] = to_tf32(v.w);
    }
    __syncthreads();

    for (int ch = 0; ch < 8; ch++) {
        float4 pv[4];
        if (ch + 1 < 8) {
#pragma unroll
            for (int i = 0; i < 4; i++) {
                int u = tid + i * 256;
                int r = u >> 4, q = u & 15;
                pv[i] = *(const float4*)(vsrc + ((ch + 1) * 64 + r) * HD_ + q * 4);
            }
        }
#pragma unroll
        for (int ks = 0; ks < 8; ks++) {
            wmma::fragment<wmma::matrix_a, 16, 16, 8, wmma::precision::tf32, wmma::row_major> af;
            wmma::fragment<wmma::matrix_b, 16, 16, 8, wmma::precision::tf32, wmma::row_major> bf[2];
            wmma::load_matrix_sync(af, Ss + (wm * 16) * AS_LD + ch * 64 + ks * 8, AS_LD);
#pragma unroll
            for (int j = 0; j < 2; j++)
                wmma::load_matrix_sync(bf[j], KVs + (ks * 8) * AQ_LD + wn * 32 + j * 16, AQ_LD);
#pragma unroll
            for (int j = 0; j < 2; j++)
                wmma::mma_sync(oacc[j], af, bf[j], oacc[j]);
        }
        if (ch + 1 < 8) {
            __syncthreads();
#pragma unroll
            for (int i = 0; i < 4; i++) {
                int u = tid + i * 256;
                int r = u >> 4, q = u & 15;
                float* d = KVs + r * AQ_LD + q * 4;
                d[0] = to_tf32(pv[i].x); d[1] = to_tf32(pv[i].y);
                d[2] = to_tf32(pv[i].z); d[3] = to_tf32(pv[i].w);
            }
            __syncthreads();
        }
    }

    // ---- write O tile to g_attn (b, c, h*hd layout) --------------------------
    int b = bh >> 4, h = bh & 15;
    float* obase = g_attn + ((size_t)b * C_ + qbase + wm * 16) * D_ + h * HD_ + wn * 32;
#pragma unroll
    for (int j = 0; j < 2; j++)
        wmma::store_matrix_sync(obase + j * 16, oacc[j], D_, wmma::mem_row_major);
}

// ---------------- rope base init ----------------------------------------------
__global__ void init_base_kernel() {
    int i = threadIdx.x;
    double end = 2595.0 * log10(21.0);
    double v = (double)i * (end / 31.0);
    double scale = pow(10.0, v / 2595.0) - 1.0;
    g_base[i] = (float)(200.0 * scale / 1000.0);
}

// ---------------- dual rmsnorm --------------------------------------------------
__global__ void rmsnorm_dual_kernel(const float* __restrict__ x,
                                    const float* __restrict__ wq,
                                    const float* __restrict__ wkv) {
    int row = blockIdx.x;
    int tid = threadIdx.x;
    const float* xr = x + (size_t)row * D_;
    float v[4]; float ss = 0.f;
#pragma unroll
    for (int i = 0; i < 4; i++) { v[i] = xr[tid + i*256]; ss += v[i]*v[i]; }
#pragma unroll
    for (int o = 16; o; o >>= 1) ss += __shfl_xor_sync(0xffffffffu, ss, o);
    __shared__ float red[8];
    if ((tid & 31) == 0) red[tid >> 5] = ss;
    __syncthreads();
    float tot = 0.f;
#pragma unroll
    for (int i = 0; i < 8; i++) tot += red[i];
    float r = rsqrtf(tot * (1.f / D_) + EPS_);

    int b = row >> 11, c = row & (C_ - 1);
    bool dokv = (c & (STRIDE_ - 1)) == 0;
    int krow = b * KS_ + (c >> 2);
#pragma unroll
    for (int i = 0; i < 4; i++) {
        int col = tid + i*256;
        float n = v[i] * r;
        g_xqn[(size_t)row * D_ + col] = n * wq[col];
        if (dokv) g_xkvn[(size_t)krow * D_ + col] = n * wkv[col];
    }
}

// ---------------- rope + per-head rmsnorm on Q ----------------------------------
__global__ void rope_norm_q_kernel(const float* __restrict__ ln_w) {
    int row = blockIdx.x;
    int h = threadIdx.x >> 5;
    int lane = threadIdx.x & 31;
    int b = row >> 11, c = row & (C_ - 1);
    const float* qp = g_q + (size_t)row * D_ + h * HD_;
    float a  = qp[2 * lane];
    float bb = qp[2 * lane + 1];
    float fr = (float)c * g_base[lane];
    float sn, cs; sincosf(fr, &sn, &cs);
    float na = a * cs - bb * sn;
    float nb = a * sn + bb * cs;
    float ss = na * na + nb * nb;
#pragma unroll
    for (int o = 16; o; o >>= 1) ss += __shfl_xor_sync(0xffffffffu, ss, o);
    float r = rsqrtf(ss * (1.f / HD_) + EPS_);
    size_t ob = (((size_t)(b * H_ + h) * C_) + c) * HD_ + 2 * lane;
    g_qn[ob]     = na * r * ln_w[2 * lane];
    g_qn[ob + 1] = nb * r * ln_w[2 * lane + 1];
}

// ---------------- rope + rmsnorm on K + V copy ----------------------------------
__global__ void kv_process_kernel(const float* __restrict__ ln_w) {
    int idx = blockIdx.x;
    int b = idx >> 9, ks = idx & (KS_ - 1);
    int h = threadIdx.x >> 5;
    int lane = threadIdx.x & 31;
    const float* row = g_kv + (size_t)idx * (2 * D_);
    float a  = row[h * HD_ + 2 * lane];
    float bb = row[h * HD_ + 2 * lane + 1];
    float fr = (float)(ks * STRIDE_) * g_base[lane];
    float sn, cs; sincosf(fr, &sn, &cs);
    float na = a * cs - bb * sn;
    float nb = a * sn + bb * cs;
    float ss = na * na + nb * nb;
#pragma unroll
    for (int o = 16; o; o >>= 1) ss += __shfl_xor_sync(0xffffffffu, ss, o);
    float r = rsqrtf(ss * (1.f / HD_) + EPS_);
    size_t kb = (((size_t)(b * H_ + h) * KS_) + ks) * HD_;
    g_kn[kb + 2 * lane]     = na * r * ln_w[2 * lane];
    g_kn[kb + 2 * lane + 1] = nb * r * ln_w[2 * lane + 1];
    g_v[kb + lane]      = row[D_ + h * HD_ + lane];
    g_v[kb + lane + 32] = row[D_ + h * HD_ + lane + 32];
}

// ---------------- launcher -------------------------------------------------------
extern "C" void kernel_launch(void* const* d_in, const int* in_sizes, int n_in,
                              void* d_out, int out_size) {
    const float* x       = (const float*)d_in[0];
    const float* rmsq_w  = (const float*)d_in[1];
    const float* q_w     = (const float*)d_in[2];
    const float* q_b     = (const float*)d_in[3];
    const float* rmskv_w = (const float*)d_in[4];
    const float* kv_w    = (const float*)d_in[5];
    const float* kv_b    = (const float*)d_in[6];
    const float* ln_w    = (const float*)d_in[7];
    const float* out_w   = (const float*)d_in[8];
    const float* out_b   = (const float*)d_in[9];
    float* out = (float*)d_out;

    void *p_xqn, *p_xkvn, *p_q, *p_kv, *p_attn;
    cudaGetSymbolAddress(&p_xqn,  g_xqn);
    cudaGetSymbolAddress(&p_xkvn, g_xkvn);
    cudaGetSymbolAddress(&p_q,    g_q);
    cudaGetSymbolAddress(&p_kv,   g_kv);
    cudaGetSymbolAddress(&p_attn, g_attn);

    const int GEMM_SMEM = 73728;   // max(mainloop 70656, epilogue 8*64*36*4)
    const int ATTN_SMEM = 169984;
    cudaFuncSetAttribute(gemm_wmma_kernel,
                         cudaFuncAttributeMaxDynamicSharedMemorySize, GEMM_SMEM);
    cudaFuncSetAttribute(attention_wmma_kernel,
                         cudaFuncAttributeMaxDynamicSharedMemorySize, ATTN_SMEM);

    init_base_kernel<<<1, 32>>>();
    rmsnorm_dual_kernel<<<B_ * C_, 256>>>(x, rmsq_w, rmskv_w);

    // q = xqn @ q_w + q_b : M=8192, N=1024, K=1024
    gemm_wmma_kernel<<<dim3(D_ / 128, (B_ * C_) / 128), 256, GEMM_SMEM>>>(
        (const float*)p_xqn, q_w, q_b, (float*)p_q, B_ * C_, D_, D_);

    // kv = xkvn @ kv_w + kv_b : M=2048, N=2048, K=1024
    gemm_wmma_kernel<<<dim3((2 * D_) / 128, (B_ * KS_) / 128), 256, GEMM_SMEM>>>(
        (const float*)p_xkvn, kv_w, kv_b, (float*)p_kv, B_ * KS_, 2 * D_, D_);

    rope_norm_q_kernel<<<B_ * C_, 512>>>(ln_w);
    kv_process_kernel<<<B_ * KS_, 512>>>(ln_w);

    attention_wmma_kernel<<<dim3(C_ / 64, B_ * H_), 256, ATTN_SMEM>>>();

    // out = attn @ out_w + out_b : M=8192, N=1024, K=1024
    gemm_wmma_kernel<<<dim3(D_ / 128, (B_ * C_) / 128), 256, GEMM_SMEM>>>(
        (const float*)p_attn, out_w, out_b, out, B_ * C_, D_, D_);
}

// round 5
// speedup vs baseline: 2.1243x; 1.0724x over previous
#include <cuda_runtime.h>
#include <math.h>
#include <stdint.h>
#include <mma.h>

using namespace nvcuda;

#define B_   4
#define C_   2048
#define D_   1024
#define H_   16
#define HD_  64
#define KS_  512
#define STRIDE_ 4
#define EPS_ 1.1920929e-07f

// ---------------- scratch (device globals) -----------------------------------
__device__ float g_xqn [B_*C_*D_];        // tf32-rounded rmsnorm_q
__device__ float g_xkvn[B_*KS_*D_];       // tf32-rounded rmsnorm_kv (strided rows)
__device__ float g_q   [B_*C_*D_];
__device__ float g_kv  [B_*KS_*2*D_];
__device__ float g_qn  [B_*H_*C_*HD_];    // tf32-rounded, pre-scaled by 0.125
__device__ float g_kn  [B_*H_*KS_*HD_];   // tf32-rounded
__device__ float g_v   [B_*H_*KS_*HD_];   // tf32-rounded
__device__ float g_attn[B_*C_*D_];        // tf32-rounded
__device__ float g_wq  [D_*D_];           // tf32 weight copies
__device__ float g_wkv [D_*2*D_];
__device__ float g_wo  [D_*D_];
__device__ float g_base[HD_/2];

__device__ __forceinline__ float to_tf32(float x) {
    float r; asm("cvt.rna.tf32.f32 %0, %1;" : "=f"(r) : "f"(x)); return r;
}
__device__ __forceinline__ uint32_t smem_u32(const void* p) {
    uint32_t a;
    asm("{ .reg .u64 t; cvta.to.shared.u64 t, %1; cvt.u32.u64 %0, t; }"
        : "=r"(a) : "l"(p));
    return a;
}
__device__ __forceinline__ void cp16(uint32_t dst, const void* src) {
    asm volatile("cp.async.cg.shared.global [%0], [%1], 16;" :: "r"(dst), "l"(src));
}
#define CP_COMMIT() asm volatile("cp.async.commit_group;" ::: "memory")
#define CP_WAIT1()  asm volatile("cp.async.wait_group 1;" ::: "memory")
#define CP_WAIT0()  asm volatile("cp.async.wait_group 0;" ::: "memory")

// =================== wmma tf32 GEMM (cp.async double-buffered) ================
// 128x128 CTA tile, K-chunk 32, 8 warps (2m x 4n), warp tile 64x32.
#define GA_LD 36     // 144B rows (16B multiple)
#define GB_LD 140    // 560B rows (16B multiple)
#define EP_LD 36
__global__ __launch_bounds__(256, 2) void gemm_wmma_kernel(
        const float* __restrict__ A, const float* __restrict__ W,
        const float* __restrict__ bias, float* __restrict__ C,
        int M, int N, int K) {
    extern __shared__ float sm[];
    float* As = sm;                       // 2*128*36 = 9216 floats
    float* Bs = sm + 2 * 128 * GA_LD;     // 2*32*140 = 8960 floats
    uint32_t asu = smem_u32(As), bsu = smem_u32(Bs);

    int tid = threadIdx.x;
    int warp = tid >> 5;
    int lane = tid & 31;
    int wm = warp & 1;
    int wn = warp >> 1;
    int m0 = blockIdx.y * 128;
    int n0 = blockIdx.x * 128;
    int nc = K >> 5;

#define G_STAGE(cc, bb) do { \
    uint32_t abase = asu + (uint32_t)(bb) * (128 * GA_LD * 4); \
    _Pragma("unroll") \
    for (int i = 0; i < 4; i++) { \
        int u = tid + i * 256; int r = u >> 3, q = u & 7; \
        cp16(abase + (uint32_t)(r * GA_LD + q * 4) * 4, \
             A + (size_t)(m0 + r) * K + (cc) * 32 + q * 4); \
    } \
    uint32_t bbase = bsu + (uint32_t)(bb) * (32 * GB_LD * 4); \
    _Pragma("unroll") \
    for (int i = 0; i < 4; i++) { \
        int u = tid + i * 256; int r = u >> 5, q = u & 31; \
        cp16(bbase + (uint32_t)(r * GB_LD + q * 4) * 4, \
             W + (size_t)((cc) * 32 + r) * N + n0 + q * 4); \
    } \
    CP_COMMIT(); \
} while (0)

    wmma::fragment<wmma::accumulator, 16, 16, 8, float> acc[4][2];
#pragma unroll
    for (int i = 0; i < 4; i++)
#pragma unroll
        for (int j = 0; j < 2; j++) wmma::fill_fragment(acc[i][j], 0.0f);

    G_STAGE(0, 0);
    G_STAGE(1, 1);

    for (int c = 0; c < nc; c++) {
        if (c + 1 < nc) { CP_WAIT1(); } else { CP_WAIT0(); }
        __syncthreads();
        const float* Ab = As + (c & 1) * (128 * GA_LD);
        const float* Bb = Bs + (c & 1) * (32 * GB_LD);
#pragma unroll
        for (int ks = 0; ks < 4; ks++) {
            wmma::fragment<wmma::matrix_a, 16, 16, 8, wmma::precision::tf32, wmma::row_major> af[4];
            wmma::fragment<wmma::matrix_b, 16, 16, 8, wmma::precision::tf32, wmma::row_major> bf[2];
#pragma unroll
            for (int i = 0; i < 4; i++)
                wmma::load_matrix_sync(af[i], Ab + (wm * 64 + i * 16) * GA_LD + ks * 8, GA_LD);
#pragma unroll
            for (int j = 0; j < 2; j++)
                wmma::load_matrix_sync(bf[j], Bb + (ks * 8) * GB_LD + wn * 32 + j * 16, GB_LD);
#pragma unroll
            for (int i = 0; i < 4; i++)
#pragma unroll
                for (int j = 0; j < 2; j++)
                    wmma::mma_sync(acc[i][j], af[i], bf[j], acc[i][j]);
        }
        __syncthreads();
        if (c + 2 < nc) G_STAGE(c + 2, c & 1);
    }

    // epilogue: per-warp smem staging + bias + coalesced stores
    float* wsm = sm + warp * (64 * EP_LD);
#pragma unroll
    for (int i = 0; i < 4; i++)
#pragma unroll
        for (int j = 0; j < 2; j++)
            wmma::store_matrix_sync(wsm + (i * 16) * EP_LD + j * 16, acc[i][j], EP_LD,
                                    wmma::mem_row_major);
    __syncwarp();
#pragma unroll
    for (int r2 = 0; r2 < 2; r2++) {
        int r = r2 * 32 + lane;
        float* crow = C + (size_t)(m0 + wm * 64 + r) * N + n0 + wn * 32;
        const float* srow = wsm + r * EP_LD;
        const float* brow = bias + n0 + wn * 32;
#pragma unroll
        for (int q = 0; q < 8; q++) {
            float4 v;
            v.x = srow[q * 4 + 0] + brow[q * 4 + 0];
            v.y = srow[q * 4 + 1] + brow[q * 4 + 1];
            v.z = srow[q * 4 + 2] + brow[q * 4 + 2];
            v.w = srow[q * 4 + 3] + brow[q * 4 + 3];
            *(float4*)(crow + q * 4) = v;
        }
    }
#undef G_STAGE
}

// =================== fused wmma attention (512 threads, cp.async) ============
// block: one bh, 64 q rows. 16 warps: wm = warp&3 (m), wn = warp>>2 (n)
#define AQ_LD 72
#define AS_LD 520
__global__ __launch_bounds__(512) void attention_wmma_kernel() {
    extern __shared__ float sm[];
    float* Qs  = sm;                       // 64*72   = 4608
    float* KVs = sm + 4608;                // 2*64*72 = 9216
    float* Ss  = sm + 13824;               // 64*520  = 33280
    uint32_t qsu = smem_u32(Qs), kvu = smem_u32(KVs);

    int tid = threadIdx.x;
    int warp = tid >> 5;
    int lane = tid & 31;
    int wm = warp & 3;
    int wn = warp >> 2;
    int bh = blockIdx.y;
    int qbase = blockIdx.x * 64;

    const float* qsrc = g_qn + ((size_t)bh * C_ + qbase) * HD_;
    const float* ksrc = g_kn + (size_t)bh * KS_ * HD_;
    const float* vsrc = g_v  + (size_t)bh * KS_ * HD_;

#define A_STAGE(src, ch, bb) do { \
    uint32_t base = kvu + (uint32_t)(bb) * (64 * AQ_LD * 4); \
    _Pragma("unroll") \
    for (int i = 0; i < 2; i++) { \
        int u = tid + i * 512; int r = u >> 4, q = u & 15; \
        cp16(base + (uint32_t)(r * AQ_LD + q * 4) * 4, \
             (src) + ((ch) * 64 + r) * HD_ + q * 4); \
    } \
    CP_COMMIT(); \
} while (0)

    // prologue: Q + K chunk0 (group 0), K chunk1 (group 1)
#pragma unroll
    for (int i = 0; i < 2; i++) {
        int u = tid + i * 512; int r = u >> 4, q = u & 15;
        cp16(qsu + (uint32_t)(r * AQ_LD + q * 4) * 4, qsrc + r * HD_ + q * 4);
    }
    {
        uint32_t base = kvu;
#pragma unroll
        for (int i = 0; i < 2; i++) {
            int u = tid + i * 512; int r = u >> 4, q = u & 15;
            cp16(base + (uint32_t)(r * AQ_LD + q * 4) * 4, ksrc + r * HD_ + q * 4);
        }
        CP_COMMIT();
    }
    A_STAGE(ksrc, 1, 1);

    // ---- scores: S[64][512] = Q @ K^T (Q pre-scaled by 0.125) ---------------
    for (int ch = 0; ch < 8; ch++) {
        if (ch + 1 < 8) { CP_WAIT1(); } else { CP_WAIT0(); }
        __syncthreads();
        const float* Kb = KVs + (ch & 1) * (64 * AQ_LD);
        wmma::fragment<wmma::accumulator, 16, 16, 8, float> sacc;
        wmma::fill_fragment(sacc, 0.0f);
#pragma unroll
        for (int ks = 0; ks < 8; ks++) {
            wmma::fragment<wmma::matrix_a, 16, 16, 8, wmma::precision::tf32, wmma::row_major> af;
            wmma::fragment<wmma::matrix_b, 16, 16, 8, wmma::precision::tf32, wmma::col_major> bf;
            wmma::load_matrix_sync(af, Qs + (wm * 16) * AQ_LD + ks * 8, AQ_LD);
            wmma::load_matrix_sync(bf, Kb + (wn * 16) * AQ_LD + ks * 8, AQ_LD);
            wmma::mma_sync(sacc, af, bf, sacc);
        }
        wmma::store_matrix_sync(Ss + (wm * 16) * AS_LD + ch * 64 + wn * 16,
                                sacc, AS_LD, wmma::mem_row_major);
        __syncthreads();
        if (ch + 2 < 8) A_STAGE(ksrc, ch + 2, ch & 1);
    }

    // prefetch V chunks 0,1 while softmax runs
    A_STAGE(vsrc, 0, 0);
    A_STAGE(vsrc, 1, 1);

    // ---- softmax: warp w handles rows w*4..w*4+3, store P as tf32 -----------
    for (int rr = 0; rr < 4; rr++) {
        int r = warp * 4 + rr;
        float* row = Ss + r * AS_LD;
        float m = -1e30f;
#pragma unroll
        for (int k = 0; k < 16; k++) m = fmaxf(m, row[lane + k * 32]);
#pragma unroll
        for (int o = 16; o; o >>= 1) m = fmaxf(m, __shfl_xor_sync(0xffffffffu, m, o));
        float sum = 0.f;
        float e[16];
#pragma unroll
        for (int k = 0; k < 16; k++) { e[k] = expf(row[lane + k * 32] - m); sum += e[k]; }
#pragma unroll
        for (int o = 16; o; o >>= 1) sum += __shfl_xor_sync(0xffffffffu, sum, o);
        float inv = 1.f / sum;
#pragma unroll
        for (int k = 0; k < 16; k++) row[lane + k * 32] = to_tf32(e[k] * inv);
    }

    // ---- O = P @ V ------------------------------------------------------------
    wmma::fragment<wmma::accumulator, 16, 16, 8, float> oacc;
    wmma::fill_fragment(oacc, 0.0f);
    for (int ch = 0; ch < 8; ch++) {
        if (ch + 1 < 8) { CP_WAIT1(); } else { CP_WAIT0(); }
        __syncthreads();
        const float* Vb = KVs + (ch & 1) * (64 * AQ_LD);
#pragma unroll
        for (int ks = 0; ks < 8; ks++) {
            wmma::fragment<wmma::matrix_a, 16, 16, 8, wmma::precision::tf32, wmma::row_major> af;
            wmma::fragment<wmma::matrix_b, 16, 16, 8, wmma::precision::tf32, wmma::row_major> bf;
            wmma::load_matrix_sync(af, Ss + (wm * 16) * AS_LD + ch * 64 + ks * 8, AS_LD);
            wmma::load_matrix_sync(bf, Vb + (ks * 8) * AQ_LD + wn * 16, AQ_LD);
            wmma::mma_sync(oacc, af, bf, oacc);
        }
        __syncthreads();
        if (ch + 2 < 8) A_STAGE(vsrc, ch + 2, ch & 1);
    }

    // ---- write O tile (tf32-rounded for the out-projection GEMM) -------------
    int b = bh >> 4, h = bh & 15;
#pragma unroll
    for (int t = 0; t < oacc.num_elements; t++) oacc.x[t] = to_tf32(oacc.x[t]);
    float* obase = g_attn + ((size_t)b * C_ + qbase + wm * 16) * D_ + h * HD_ + wn * 16;
    wmma::store_matrix_sync(obase, oacc, D_, wmma::mem_row_major);
#undef A_STAGE
}

// ---------------- rope base init ----------------------------------------------
__global__ void init_base_kernel() {
    int i = threadIdx.x;
    double end = 2595.0 * log10(21.0);
    double v = (double)i * (end / 31.0);
    double scale = pow(10.0, v / 2595.0) - 1.0;
    g_base[i] = (float)(200.0 * scale / 1000.0);
}

// ---------------- weight tf32 conversion ----------------------------------------
__global__ void cvt_kernel(const float* __restrict__ s, float* __restrict__ d, int n4) {
    int i = blockIdx.x * 256 + threadIdx.x;
    if (i < n4) {
        float4 v = ((const float4*)s)[i];
        v.x = to_tf32(v.x); v.y = to_tf32(v.y);
        v.z = to_tf32(v.z); v.w = to_tf32(v.w);
        ((float4*)d)[i] = v;
    }
}

// ---------------- dual rmsnorm (tf32-rounded outputs) ----------------------------
__global__ void rmsnorm_dual_kernel(const float* __restrict__ x,
                                    const float* __restrict__ wq,
                                    const float* __restrict__ wkv) {
    int row = blockIdx.x;
    int tid = threadIdx.x;
    const float* xr = x + (size_t)row * D_;
    float v[4]; float ss = 0.f;
#pragma unroll
    for (int i = 0; i < 4; i++) { v[i] = xr[tid + i*256]; ss += v[i]*v[i]; }
#pragma unroll
    for (int o = 16; o; o >>= 1) ss += __shfl_xor_sync(0xffffffffu, ss, o);
    __shared__ float red[8];
    if ((tid & 31) == 0) red[tid >> 5] = ss;
    __syncthreads();
    float tot = 0.f;
#pragma unroll
    for (int i = 0; i < 8; i++) tot += red[i];
    float r = rsqrtf(tot * (1.f / D_) + EPS_);

    int b = row >> 11, c = row & (C_ - 1);
    bool dokv = (c & (STRIDE_ - 1)) == 0;
    int krow = b * KS_ + (c >> 2);
#pragma unroll
    for (int i = 0; i < 4; i++) {
        int col = tid + i*256;
        float n = v[i] * r;
        g_xqn[(size_t)row * D_ + col] = to_tf32(n * wq[col]);
        if (dokv) g_xkvn[(size_t)krow * D_ + col] = to_tf32(n * wkv[col]);
    }
}

// ---------------- rope + per-head rmsnorm on Q (pre-scaled, tf32) ---------------
__global__ void rope_norm_q_kernel(const float* __restrict__ ln_w) {
    int row = blockIdx.x;
    int h = threadIdx.x >> 5;
    int lane = threadIdx.x & 31;
    int b = row >> 11, c = row & (C_ - 1);
    const float* qp = g_q + (size_t)row * D_ + h * HD_;
    float a  = qp[2 * lane];
    float bb = qp[2 * lane + 1];
    float fr = (float)c * g_base[lane];
    float sn, cs; sincosf(fr, &sn, &cs);
    float na = a * cs - bb * sn;
    float nb = a * sn + bb * cs;
    float ss = na * na + nb * nb;
#pragma unroll
    for (int o = 16; o; o >>= 1) ss += __shfl_xor_sync(0xffffffffu, ss, o);
    float r = rsqrtf(ss * (1.f / HD_) + EPS_);
    size_t ob = (((size_t)(b * H_ + h) * C_) + c) * HD_ + 2 * lane;
    g_qn[ob]     = to_tf32(0.125f * (na * r * ln_w[2 * lane]));
    g_qn[ob + 1] = to_tf32(0.125f * (nb * r * ln_w[2 * lane + 1]));
}

// ---------------- rope + rmsnorm on K + V copy (tf32) ---------------------------
__global__ void kv_process_kernel(const float* __restrict__ ln_w) {
    int idx = blockIdx.x;
    int b = idx >> 9, ks = idx & (KS_ - 1);
    int h = threadIdx.x >> 5;
    int lane = threadIdx.x & 31;
    const float* row = g_kv + (size_t)idx * (2 * D_);
    float a  = row[h * HD_ + 2 * lane];
    float bb = row[h * HD_ + 2 * lane + 1];
    float fr = (float)(ks * STRIDE_) * g_base[lane];
    float sn, cs; sincosf(fr, &sn, &cs);
    float na = a * cs - bb * sn;
    float nb = a * sn + bb * cs;
    float ss = na * na + nb * nb;
#pragma unroll
    for (int o = 16; o; o >>= 1) ss += __shfl_xor_sync(0xffffffffu, ss, o);
    float r = rsqrtf(ss * (1.f / HD_) + EPS_);
    size_t kb = (((size_t)(b * H_ + h) * KS_) + ks) * HD_;
    g_kn[kb + 2 * lane]     = to_tf32(na * r * ln_w[2 * lane]);
    g_kn[kb + 2 * lane + 1] = to_tf32(nb * r * ln_w[2 * lane + 1]);
    g_v[kb + lane]      = to_tf32(row[D_ + h * HD_ + lane]);
    g_v[kb + lane + 32] = to_tf32(row[D_ + h * HD_ + lane + 32]);
}

// ---------------- launcher -------------------------------------------------------
extern "C" void kernel_launch(void* const* d_in, const int* in_sizes, int n_in,
                              void* d_out, int out_size) {
    const float* x       = (const float*)d_in[0];
    const float* rmsq_w  = (const float*)d_in[1];
    const float* q_w     = (const float*)d_in[2];
    const float* q_b     = (const float*)d_in[3];
    const float* rmskv_w = (const float*)d_in[4];
    const float* kv_w    = (const float*)d_in[5];
    const float* kv_b    = (const float*)d_in[6];
    const float* ln_w    = (const float*)d_in[7];
    const float* out_w   = (const float*)d_in[8];
    const float* out_b   = (const float*)d_in[9];
    float* out = (float*)d_out;

    void *p_xqn, *p_xkvn, *p_q, *p_kv, *p_attn, *p_wq, *p_wkv, *p_wo;
    cudaGetSymbolAddress(&p_xqn,  g_xqn);
    cudaGetSymbolAddress(&p_xkvn, g_xkvn);
    cudaGetSymbolAddress(&p_q,    g_q);
    cudaGetSymbolAddress(&p_kv,   g_kv);
    cudaGetSymbolAddress(&p_attn, g_attn);
    cudaGetSymbolAddress(&p_wq,   g_wq);
    cudaGetSymbolAddress(&p_wkv,  g_wkv);
    cudaGetSymbolAddress(&p_wo,   g_wo);

    const int GEMM_SMEM = 73728;    // max(mainloop 72704, epilogue 73728)
    const int ATTN_SMEM = 188416;   // Qs + 2*KV + Ss
    cudaFuncSetAttribute(gemm_wmma_kernel,
                         cudaFuncAttributeMaxDynamicSharedMemorySize, GEMM_SMEM);
    cudaFuncSetAttribute(attention_wmma_kernel,
                         cudaFuncAttributeMaxDynamicSharedMemorySize, ATTN_SMEM);

    init_base_kernel<<<1, 32>>>();
    cvt_kernel<<<(D_*D_/4 + 255)/256, 256>>>(q_w,   (float*)p_wq,  D_*D_/4);
    cvt_kernel<<<(D_*2*D_/4 + 255)/256, 256>>>(kv_w, (float*)p_wkv, D_*2*D_/4);
    cvt_kernel<<<(D_*D_/4 + 255)/256, 256>>>(out_w, (float*)p_wo,  D_*D_/4);
    rmsnorm_dual_kernel<<<B_ * C_, 256>>>(x, rmsq_w, rmskv_w);

    // q = xqn @ q_w + q_b : M=8192, N=1024, K=1024
    gemm_wmma_kernel<<<dim3(D_ / 128, (B_ * C_) / 128), 256, GEMM_SMEM>>>(
        (const float*)p_xqn, (const float*)p_wq, q_b, (float*)p_q, B_ * C_, D_, D_);

    // kv = xkvn @ kv_w + kv_b : M=2048, N=2048, K=1024
    gemm_wmma_kernel<<<dim3((2 * D_) / 128, (B_ * KS_) / 128), 256, GEMM_SMEM>>>(
        (const float*)p_xkvn, (const float*)p_wkv, kv_b, (float*)p_kv, B_ * KS_, 2 * D_, D_);

    rope_norm_q_kernel<<<B_ * C_, 512>>>(ln_w);
    kv_process_kernel<<<B_ * KS_, 512>>>(ln_w);

    attention_wmma_kernel<<<dim3(C_ / 64, B_ * H_), 512, ATTN_SMEM>>>();

    // out = attn @ out_w + out_b : M=8192, N=1024, K=1024
    gemm_wmma_kernel<<<dim3(D_ / 128, (B_ * C_) / 128), 256, GEMM_SMEM>>>(
        (const float*)p_attn, (const float*)p_wo, out_b, out, B_ * C_, D_, D_);
}